// round 15
// baseline (speedup 1.0000x reference)
#include <cuda_runtime.h>

#define FULL 0xffffffffu
typedef unsigned long long u64;

static constexpr int B_ = 64;
static constexpr int S_ = 12;
static constexpr int N_ = 207;
static constexpr int F_ = 2;
static constexpr int NCIRC = B_ * N_;       // 13248
static constexpr int CPB = 16;              // circuits per 256-thread block
static constexpr float PI_F = 3.14159265358979323846f;

// Each warp-PAIR handles 4 circuits: even warp = re component, odd warp = im.
// Within a warp: 4 groups of 8 lanes, one circuit per group.
// Flat j (8 bits) = (g << 5) | r;  g = lane & 7, r (5 bits).
// qubit -> j-bit: q0->7 q5->6 q7->5 (lane g bits 2,1,0)
//                 q1->4 q2->3 q3->2 q4->1 q6->0 (r bits 4..0)
// Packed state: float2 st[16], k (4 bits) = r>>1 (q1,q2,q3,q4), intra half = q6.

__device__ __forceinline__ float shx(float v, int m) { return __shfl_xor_sync(FULL, v, m); }

__device__ __forceinline__ float2 shx2f(float2 v, int m) {
    return make_float2(shx(v.x, m), shx(v.y, m));
}
__device__ __forceinline__ float2 ffma2(float2 a, float2 b, float2 c) {
    float2 d;
    asm("fma.rn.f32x2 %0, %1, %2, %3;"
        : "=l"(*reinterpret_cast<u64*>(&d))
        : "l"(*reinterpret_cast<u64*>(&a)),
          "l"(*reinterpret_cast<u64*>(&b)),
          "l"(*reinterpret_cast<u64*>(&c)));
    return d;
}
__device__ __forceinline__ float2 fmul2(float2 a, float2 b) {
    float2 d;
    asm("mul.rn.f32x2 %0, %1, %2;"
        : "=l"(*reinterpret_cast<u64*>(&d))
        : "l"(*reinterpret_cast<u64*>(&a)),
          "l"(*reinterpret_cast<u64*>(&b)));
    return d;
}
__device__ __forceinline__ float2 fadd2(float2 a, float2 b) {
    float2 d;
    asm("add.rn.f32x2 %0, %1, %2;"
        : "=l"(*reinterpret_cast<u64*>(&d))
        : "l"(*reinterpret_cast<u64*>(&a)),
          "l"(*reinterpret_cast<u64*>(&b)));
    return d;
}

// ---- packed fused conv pair, both qubits k-bits (KA first, KB second) ----
template<int KA, int KB>
__device__ __forceinline__ void conv_rr2(float2 (&st)[16], const float2* __restrict__ U2) {
    float2 u[16];
    #pragma unroll
    for (int i = 0; i < 8; ++i) {
        float4 t = ((const float4*)U2)[i];
        u[2 * i]     = make_float2(t.x, t.y);
        u[2 * i + 1] = make_float2(t.z, t.w);
    }
    constexpr int ma = 1 << KA, mb = 1 << KB;
    #pragma unroll
    for (int k0 = 0; k0 < 16; ++k0) if (!(k0 & (ma | mb))) {
        const int i1 = k0 | mb, i2 = k0 | ma, i3 = k0 | ma | mb;
        float2 v0 = st[k0], v1 = st[i1], v2 = st[i2], v3 = st[i3];
        st[k0] = ffma2(u[0],  v0, ffma2(u[1],  v1, ffma2(u[2],  v2, fmul2(u[3],  v3))));
        st[i1] = ffma2(u[4],  v0, ffma2(u[5],  v1, ffma2(u[6],  v2, fmul2(u[7],  v3))));
        st[i2] = ffma2(u[8],  v0, ffma2(u[9],  v1, ffma2(u[10], v2, fmul2(u[11], v3))));
        st[i3] = ffma2(u[12], v0, ffma2(u[13], v1, ffma2(u[14], v2, fmul2(u[15], v3))));
    }
}

// ---- packed fused conv pair, one qubit on lane bit LBIT, one on k-bit KB.
// Coefficients pre-arranged (duplicated) in shared: T2[a*8 .. a*8+7].
template<int LBIT, int KB>
__device__ __forceinline__ void conv_mx2(float2 (&st)[16], const float2* __restrict__ T2, int lane) {
    constexpr int Lm = 1 << LBIT, mb = 1 << KB;
    const int a = (lane >> LBIT) & 1;
    float2 u[8];
    #pragma unroll
    for (int i = 0; i < 4; ++i) {
        float4 t = ((const float4*)(T2 + a * 8))[i];
        u[2 * i]     = make_float2(t.x, t.y);
        u[2 * i + 1] = make_float2(t.z, t.w);
    }
    #pragma unroll
    for (int k0 = 0; k0 < 16; ++k0) if (!(k0 & mb)) {
        const int k1 = k0 | mb;
        float2 p0 = shx2f(st[k0], Lm), p1 = shx2f(st[k1], Lm);
        float2 o0 = st[k0], o1 = st[k1];
        st[k0] = ffma2(u[0], o0, ffma2(u[1], o1, ffma2(u[2], p0, fmul2(u[3], p1))));
        st[k1] = ffma2(u[4], o0, ffma2(u[5], o1, ffma2(u[6], p0, fmul2(u[7], p1))));
    }
}

// ---- packed fused conv pair: intra-pack qubit (q6) + a lane qubit ----
// x,y: basis rows of (lo,hi) halves; X: column XOR for lane-shuffled operand;
// Lmask: lane xor mask.
__device__ __forceinline__ void conv_intra(float2 (&st)[16], const float* __restrict__ Us,
                                           int x, int y, int X, int Lmask) {
    const float2 a2 = make_float2(Us[x * 4 + x],       Us[y * 4 + y]);
    const float2 b2 = make_float2(Us[x * 4 + y],       Us[y * 4 + x]);
    const float2 c2 = make_float2(Us[x * 4 + (x ^ X)], Us[y * 4 + (y ^ X)]);
    const float2 d2 = make_float2(Us[x * 4 + (y ^ X)], Us[y * 4 + (x ^ X)]);
    #pragma unroll
    for (int k = 0; k < 16; ++k) {
        float2 v = st[k];
        float2 p = shx2f(v, Lmask);
        float2 vsw = make_float2(v.y, v.x);
        float2 psw = make_float2(p.y, p.x);
        st[k] = ffma2(a2, v, ffma2(b2, vsw, ffma2(c2, p, fmul2(d2, psw))));
    }
}

__global__ __launch_bounds__(256, 3)
void qcnn_kernel(const float* __restrict__ x, const float* __restrict__ adj,
                 const float* __restrict__ w_proj, const float* __restrict__ b_proj,
                 const float* __restrict__ qp,
                 const float* __restrict__ w1, const float* __restrict__ b1,
                 const float* __restrict__ w2, const float* __restrict__ b2,
                 const float* __restrict__ w3, const float* __restrict__ b3,
                 float* __restrict__ out) {
    __shared__ alignas(16) float UUs[14][16];       // scalar fused conv matrices (intra gates)
    __shared__ alignas(16) float2 UU2[14][16];      // duplicated pairs (rr gates)
    __shared__ alignas(16) float2 UMX2[4][2][8];    // mx gates: [slot][laneBit a][8 pairs]
    __shared__ float poolc[4], pools[4];            // FULL-angle cos/sin of pool RYs
    __shared__ alignas(16) float w1s[512];          // w1 natural [64][8]
    __shared__ float4 w2p4[32 * 17];                // w2 rows padded to 68 floats
    __shared__ float4 h1buf4[CPB * 17];
    __shared__ float zbuf[CPB][8];                  // im-warp reduce-scattered z
    __shared__ float b1s[64], b2s[32], w3s[32];
    __shared__ float b3s;

    const int tid = threadIdx.x;

    // ---- build fused conv matrices U = C2 * G2 * C1 * G1 ----
    if (tid < 14) {
        const int layer = tid / 7, pi = tid - 7 * layer;
        const int base = layer * 28 + pi * 4;
        float c0, s0, c1, s1, c2, s2, c3, s3;
        sincosf(0.5f * qp[base + 0], &s0, &c0);
        sincosf(0.5f * qp[base + 1], &s1, &c1);
        sincosf(0.5f * qp[base + 2], &s2, &c2);
        sincosf(0.5f * qp[base + 3], &s3, &c3);
        float R0[2][2] = {{c0, -s0}, {s0, c0}};
        float R1[2][2] = {{c1, -s1}, {s1, c1}};
        float R2m[2][2] = {{c2, -s2}, {s2, c2}};
        float R3[2][2] = {{c3, -s3}, {s3, c3}};
        float A[4][4], G2m[4][4], Bm[4][4], Cm[4][4];
        #pragma unroll
        for (int ap = 0; ap < 2; ++ap)
        #pragma unroll
        for (int bp = 0; bp < 2; ++bp)
        #pragma unroll
        for (int aq = 0; aq < 2; ++aq)
        #pragma unroll
        for (int bq = 0; bq < 2; ++bq) {
            A[2 * ap + bp][2 * aq + bq]   = R0[ap][aq] * R1[bp][bq];
            G2m[2 * ap + bp][2 * aq + bq] = R2m[ap][aq] * R3[bp][bq];
        }
        const int sig1[4] = {0, 1, 3, 2};
        const int sig2[4] = {0, 3, 2, 1};
        #pragma unroll
        for (int xr = 0; xr < 4; ++xr)
            #pragma unroll
            for (int m = 0; m < 4; ++m) Bm[xr][m] = A[sig1[xr]][m];
        #pragma unroll
        for (int xr = 0; xr < 4; ++xr)
            #pragma unroll
            for (int m = 0; m < 4; ++m) {
                float acc = 0.f;
                #pragma unroll
                for (int y = 0; y < 4; ++y) acc = fmaf(G2m[xr][y], Bm[y][m], acc);
                Cm[xr][m] = acc;
            }
        float Uf[16];
        #pragma unroll
        for (int xr = 0; xr < 4; ++xr)
            #pragma unroll
            for (int m = 0; m < 4; ++m) {
                float u = Cm[sig2[xr]][m];
                Uf[xr * 4 + m] = u;
                UUs[tid][xr * 4 + m] = u;
                UU2[tid][xr * 4 + m] = make_float2(u, u);
            }
        // mx-gate coefficient tables for (q0,q1) [pi==0, lane qubit first]
        // and (q4,q5) [pi==2, lane qubit second].
        if (pi == 0 || pi == 2) {
            const int mxslot = layer * 2 + (pi == 0 ? 0 : 1);
            const bool lq1 = (pi == 0);
            #pragma unroll
            for (int a = 0; a < 2; ++a) {
                int r0, r1, d0, d1;
                if (lq1) { r0 = 2 * a; r1 = 2 * a + 1; d0 = 2 * (a ^ 1); d1 = d0 + 1; }
                else     { r0 = a;     r1 = 2 + a;     d0 = a ^ 1;       d1 = 2 + (a ^ 1); }
                float2* dst = &UMX2[mxslot][a][0];
                dst[0] = make_float2(Uf[r0 * 4 + r0], Uf[r0 * 4 + r0]);
                dst[1] = make_float2(Uf[r0 * 4 + r1], Uf[r0 * 4 + r1]);
                dst[2] = make_float2(Uf[r0 * 4 + d0], Uf[r0 * 4 + d0]);
                dst[3] = make_float2(Uf[r0 * 4 + d1], Uf[r0 * 4 + d1]);
                dst[4] = make_float2(Uf[r1 * 4 + r0], Uf[r1 * 4 + r0]);
                dst[5] = make_float2(Uf[r1 * 4 + r1], Uf[r1 * 4 + r1]);
                dst[6] = make_float2(Uf[r1 * 4 + d0], Uf[r1 * 4 + d0]);
                dst[7] = make_float2(Uf[r1 * 4 + d1], Uf[r1 * 4 + d1]);
            }
        }
    }
    if (tid >= 16 && tid < 20) {
        float s, c;
        sincosf(qp[56 + 2 * (tid - 16)], &s, &c);   // FULL angle (fused pooling)
        poolc[tid - 16] = c; pools[tid - 16] = s;
    }
    for (int i = tid; i < 512; i += 256) w1s[i] = w1[i];
    for (int i = tid; i < 2048; i += 256) {
        int row = i >> 6, j = i & 63;
        ((float*)w2p4)[row * 68 + j] = w2[i];
    }
    if (tid < 64) b1s[tid] = b1[tid];
    if (tid >= 64 && tid < 96) b2s[tid - 64] = b2[tid - 64];
    if (tid >= 96 && tid < 128) w3s[tid - 96] = w3[tid - 96];
    if (tid == 20) b3s = b3[0];
    __syncthreads();

    const int wid = tid >> 5;
    const int lane = tid & 31;
    const int comp = wid & 1;                 // 0 = re warp, 1 = im warp
    const int pairid = wid >> 1;              // 0..3
    const int ci = lane >> 3;                 // circuit-in-warp
    const int g = lane & 7;
    const int cb = pairid * 4 + ci;           // circuit-in-block 0..15
    const int cir = blockIdx.x * CPB + cb;
    const int b = cir / N_;
    const int n = cir - b * N_;

    // ---- angle projection: lane computes angle q = g of its circuit ----
    float av;
    {
        av = b_proj[g];
        const float* wrow = w_proj + g * (S_ * F_);
        const float* xb = x + (size_t)b * (S_ * N_ * F_) + n * F_;
        #pragma unroll
        for (int s = 0; s < S_; ++s) {
            float2 xv = *(const float2*)(xb + s * (N_ * F_));
            av = fmaf(wrow[2 * s], xv.x, av);
            av = fmaf(wrow[2 * s + 1], xv.y, av);
        }
        av = fminf(fmaxf(av, -PI_F), PI_F);
    }
    float sv, cv;
    __sincosf(0.5f * av, &sv, &cv);
    float ch[8], sh[8];
    #pragma unroll
    for (int q = 0; q < 8; ++q) {
        ch[q] = __shfl_sync(FULL, cv, (lane & 24) | q);
        sh[q] = __shfl_sync(FULL, sv, (lane & 24) | q);
    }

    // ---- graph CNOT mask ----
    const int c = n & 7;
    const int pcq = (0x50612347u >> (4 * c)) & 0xF;    // posOf[c]
    int cond = (adj[c * N_ + g] > 0.f) && (g != c);
    const unsigned bal = __ballot_sync(FULL, cond);
    const unsigned mask8 = (bal >> (ci * 8)) & 0xFFu;
    constexpr int posOf[8] = {7, 4, 3, 2, 1, 6, 0, 5};
    int M = 0;
    #pragma unroll
    for (int t = 0; t < 8; ++t) M |= (int)((mask8 >> t) & 1u) << posOf[t];
    const int glm = (M >> 5) & 7;
    const int MR = M & 31;
    unsigned bcmask = (pcq == 0) ? 0xAAAAAAAAu : (pcq == 1) ? 0xCCCCCCCCu :
                      (pcq == 2) ? 0xF0F0F0F0u : (pcq == 3) ? 0xFF00FF00u : 0xFFFF0000u;
    if (pcq >= 5) bcmask = ((g >> (pcq - 5)) & 1) ? 0xFFFFFFFFu : 0u;

    // ---- build product state DIRECTLY PERMUTED by the graph CNOTs ----
    const int bq0 = (g >> 2) & 1, bq5 = (g >> 1) & 1, bq7 = g & 1;
    const int gp = g ^ glm;
    const int pp0 = (gp >> 2) & 1, pp5 = (gp >> 1) & 1, pp7 = gp & 1;

    const float magL0 = (bq0 ? sh[0] : ch[0]) * (bq5 ? sh[5] : ch[5]) * (bq7 ? sh[7] : ch[7]);
    const float magL1 = (pp0 ? sh[0] : ch[0]) * (pp5 ? sh[5] : ch[5]) * (pp7 ? sh[7] : ch[7]);
    const float ssA = bq0 ? sh[4] : -sh[4];
    const float ssB = pp0 ? sh[4] : -sh[4];
    const float ssx0 = comp ? ssA : -ssA;
    const float ssx1 = comp ? ssB : -ssB;

    float u23r[4], u23i[4];
    #pragma unroll
    for (int k = 0; k < 4; ++k) {
        const float s6 = (k & 2) ? sh[6] : -sh[6];
        const float s7 = (k & 1) ? sh[7] : -sh[7];
        u23r[k] = fmaf(ch[6], ch[7], -s6 * s7);
        u23i[k] = fmaf(ch[6], s7, s6 * ch[7]);
    }
    float B0[8], B1[8];
    #pragma unroll
    for (int t = 0; t < 8; ++t) {
        const float s5 = (t & 4) ? sh[5] : -sh[5];
        const float ur = fmaf(ch[5], u23r[t & 3], -s5 * u23i[t & 3]);
        const float ui = fmaf(ch[5], u23i[t & 3], s5 * u23r[t & 3]);
        const float P = comp ? ui : ur;
        const float Q = comp ? ur : ui;
        const float mg = ((t & 4) ? sh[1] : ch[1]) * ((t & 2) ? sh[2] : ch[2])
                       * ((t & 1) ? sh[3] : ch[3]);
        B0[t] = magL0 * mg * fmaf(ch[4], P, ssx0 * Q);
        B1[t] = magL1 * mg * fmaf(ch[4], P, ssx1 * Q);
    }
    const int Mt = (MR >> 2) & 7, Mlr = MR & 3;
    float Bp[8];
    {
        float ta[8], tb[8];
        #pragma unroll
        for (int t = 0; t < 8; ++t) ta[t] = (Mt & 1) ? B1[t ^ 1] : B1[t];
        #pragma unroll
        for (int t = 0; t < 8; ++t) tb[t] = (Mt & 2) ? ta[t ^ 2] : ta[t];
        #pragma unroll
        for (int t = 0; t < 8; ++t) Bp[t] = (Mt & 4) ? tb[t ^ 4] : tb[t];
    }
    float mA[4], mp[4];
    mA[0] = ch[4] * ch[6]; mA[1] = ch[4] * sh[6];
    mA[2] = sh[4] * ch[6]; mA[3] = sh[4] * sh[6];
    {
        float tm[4];
        #pragma unroll
        for (int l = 0; l < 4; ++l) tm[l] = (Mlr & 1) ? mA[l ^ 1] : mA[l];
        #pragma unroll
        for (int l = 0; l < 4; ++l) mp[l] = (Mlr & 2) ? tm[l ^ 2] : tm[l];
    }
    // packed state: k = 2t + q4bit; halves = q6
    float2 st[16];
    #pragma unroll
    for (int t = 0; t < 8; ++t)
        #pragma unroll
        for (int q4b = 0; q4b < 2; ++q4b) {
            const int k = 2 * t + q4b;
            const int r0 = 4 * t + 2 * q4b;
            const bool bc0 = (bcmask >> r0) & 1u;
            const bool bc1 = (bcmask >> (r0 + 1)) & 1u;
            st[k].x = (bc0 ? Bp[t] : B0[t]) * (bc0 ? mp[2 * q4b]     : mA[2 * q4b]);
            st[k].y = (bc1 ? Bp[t] : B0[t]) * (bc1 ? mp[2 * q4b + 1] : mA[2 * q4b + 1]);
        }

    // ---- 2 conv layers (packed) ----
    #pragma unroll
    for (int l = 0; l < 2; ++l) {
        conv_mx2<2, 3>(st, &UMX2[l * 2 + 0][0][0], lane);            // (q0,q1)
        conv_rr2<2, 1>(st, UU2[l * 7 + 1]);                          // (q2,q3)
        conv_mx2<1, 0>(st, &UMX2[l * 2 + 1][0][0], lane);            // (q4,q5)
        conv_intra(st, UUs[l * 7 + 3], bq7, 2 + bq7, 1, 1);          // (q6,q7)
        conv_rr2<3, 2>(st, UU2[l * 7 + 4]);                          // (q1,q2)
        conv_rr2<1, 0>(st, UU2[l * 7 + 5]);                          // (q3,q4)
        conv_intra(st, UUs[l * 7 + 6], 2 * bq5, 2 * bq5 + 1, 2, 2);  // (q5,q6)
    }

    // ---- measurement with POOLING FUSED IN (packed) ----
    const float2 zero2 = make_float2(0.f, 0.f);
    float2 x2a = zero2, x4a = zero2, c0a = zero2;
    float x6 = 0.f;
    #pragma unroll
    for (int k = 0; k < 16; ++k) {
        if (!(k & 4)) x2a = ffma2(st[k], st[k | 4], x2a);   // q2 pairs (k bit2)
        if (!(k & 1)) x4a = ffma2(st[k], st[k | 1], x4a);   // q4 pairs (k bit0)
        x6 = fmaf(st[k].x, st[k].y, x6);                    // q6 pairs (intra)
        float2 p = shx2f(st[k], 4);                         // q0 cross (lane bit 2)
        c0a = ffma2(st[k], p, c0a);
    }
    const float x2 = x2a.x + x2a.y;
    const float x4 = x4a.x + x4a.y;
    const float c0x = c0a.x + c0a.y;

    // Walsh tree on packed squares (k bits: 3=q1, 2=q2, 1=q3, 0=q4; halves=q6)
    float2 s1[8], e4p = zero2;
    #pragma unroll
    for (int m = 0; m < 8; ++m) {
        float2 pa = fmul2(st[2 * m], st[2 * m]);
        float2 pb = fmul2(st[2 * m + 1], st[2 * m + 1]);
        s1[m] = fadd2(pa, pb);
        e4p = fadd2(e4p, pa);
    }
    float2 s2[4], e3p = zero2;
    #pragma unroll
    for (int n2 = 0; n2 < 4; ++n2) {
        s2[n2] = fadd2(s1[2 * n2], s1[2 * n2 + 1]);
        e3p = fadd2(e3p, s1[2 * n2]);
    }
    const float2 e2p = fadd2(s2[0], s2[2]);
    const float2 s3a = fadd2(s2[0], s2[1]);
    const float2 s3b = fadd2(s2[2], s2[3]);
    const float2 totp = fadd2(s3a, s3b);
    const float tot = totp.x + totp.y;
    const float z6r = totp.x - totp.y;
    const float z1 = (s3a.x - s3b.x) + (s3a.y - s3b.y);
    const float z2r = fmaf(2.f, e2p.x + e2p.y, -tot);
    const float z3r = fmaf(2.f, e3p.x + e3p.y, -tot);
    const float z4r = fmaf(2.f, e4p.x + e4p.y, -tot);

    float z[8];
    z[0] = fmaf(poolc[0], (bq0 ? -tot : tot), -pools[0] * c0x);
    z[2] = fmaf(poolc[1], z2r, -2.f * pools[1] * x2);
    z[4] = fmaf(poolc[2], z4r, -2.f * pools[2] * x4);
    z[6] = fmaf(poolc[3], z6r, -2.f * pools[3] * x6);
    z[1] = z1; z[3] = z3r;
    z[5] = bq5 ? -tot : tot;
    z[7] = bq7 ? -tot : tot;

    // ---- reduce-scatter over the 8-lane group: lane g ends with Z[g] ----
    float zg;
    {
        const int b2l = bq0, b1l = bq5, b0l = bq7;   // lane bits 2,1,0
        float v[4];
        #pragma unroll
        for (int j = 0; j < 4; ++j) {
            float keep = b2l ? z[j + 4] : z[j];
            float send = b2l ? z[j] : z[j + 4];
            v[j] = keep + shx(send, 4);
        }
        float u0 = (b1l ? v[2] : v[0]) + shx(b1l ? v[0] : v[2], 2);
        float u1 = (b1l ? v[3] : v[1]) + shx(b1l ? v[1] : v[3], 2);
        zg = (b0l ? u1 : u0) + shx(b0l ? u0 : u1, 1);
    }

    // im warp publishes its Z[g]; re warp combines and runs the MLP
    if (comp) zbuf[cb][g] = zg;
    __syncthreads();

    if (!comp) {
        zg += zbuf[cb][g];
        float z8[8];
        #pragma unroll
        for (int w = 0; w < 8; ++w)
            z8[w] = __shfl_sync(FULL, zg, (lane & 24) | w);

        // ---- MLP head: 8 -> 64 -> 32 -> 1 ----
        float h1v[8];
        const float* w1row = w1s + g * 64;
        #pragma unroll
        for (int i = 0; i < 8; ++i) {
            float4 wa = *(const float4*)(w1row + i * 8);
            float4 wb = *(const float4*)(w1row + i * 8 + 4);
            float acc = b1s[8 * g + i];
            acc = fmaf(wa.x, z8[0], acc); acc = fmaf(wa.y, z8[1], acc);
            acc = fmaf(wa.z, z8[2], acc); acc = fmaf(wa.w, z8[3], acc);
            acc = fmaf(wb.x, z8[4], acc); acc = fmaf(wb.y, z8[5], acc);
            acc = fmaf(wb.z, z8[6], acc); acc = fmaf(wb.w, z8[7], acc);
            h1v[i] = fmaxf(acc, 0.f);
        }
        {
            float4* dst = (float4*)((float*)h1buf4 + cb * 68 + 8 * g);
            dst[0] = make_float4(h1v[0], h1v[1], h1v[2], h1v[3]);
            dst[1] = make_float4(h1v[4], h1v[5], h1v[6], h1v[7]);
        }
        __syncwarp();

        // h2: this lane computes rows g, g+8, g+16, g+24
        float acc2[4];
        #pragma unroll
        for (int i = 0; i < 4; ++i) acc2[i] = b2s[g + 8 * i];
        const float4* h1p = h1buf4 + cb * 17;
        #pragma unroll
        for (int j4 = 0; j4 < 16; ++j4) {
            float4 h = h1p[j4];
            #pragma unroll
            for (int i = 0; i < 4; ++i) {
                float4 w = w2p4[(g + 8 * i) * 17 + j4];
                acc2[i] = fmaf(w.x, h.x, fmaf(w.y, h.y, fmaf(w.z, h.z, fmaf(w.w, h.w, acc2[i]))));
            }
        }
        float o = 0.f;
        #pragma unroll
        for (int i = 0; i < 4; ++i)
            o = fmaf(w3s[g + 8 * i], fmaxf(acc2[i], 0.f), o);
        o += shx(o, 1); o += shx(o, 2); o += shx(o, 4);
        if (g == 0) out[cir] = o + b3s;
    }
}

extern "C" void kernel_launch(void* const* d_in, const int* in_sizes, int n_in,
                              void* d_out, int out_size) {
    const float* x      = (const float*)d_in[0];
    const float* adj    = (const float*)d_in[1];
    const float* w_proj = (const float*)d_in[2];
    const float* b_proj = (const float*)d_in[3];
    const float* qp     = (const float*)d_in[4];
    const float* w1     = (const float*)d_in[5];
    const float* b1     = (const float*)d_in[6];
    const float* w2     = (const float*)d_in[7];
    const float* b2     = (const float*)d_in[8];
    const float* w3     = (const float*)d_in[9];
    const float* b3     = (const float*)d_in[10];
    float* out = (float*)d_out;

    const int blocks = NCIRC / CPB;   // 828
    qcnn_kernel<<<blocks, 256>>>(x, adj, w_proj, b_proj, qp,
                                 w1, b1, w2, b2, w3, b3, out);
}

// round 16
// speedup vs baseline: 1.0386x; 1.0386x over previous
#include <cuda_runtime.h>

#define FULL 0xffffffffu

static constexpr int B_ = 64;
static constexpr int S_ = 12;
static constexpr int N_ = 207;
static constexpr int F_ = 2;
static constexpr int NCIRC = B_ * N_;       // 13248
static constexpr int CPB = 16;              // circuits per 256-thread block
static constexpr float PI_F = 3.14159265358979323846f;

// Each WARP handles 2 circuits: lanes [0,8) re / [8,16) im of circuit A,
// lanes [16,24) re / [24,32) im of circuit B.
// Flat j (8 bits) = (g << 5) | r;  g = lane & 7, r (5 bits).
// qubit -> j-bit: q0->7 q5->6 q7->5 (lane g bits 2,1,0)
//                 q1->4 q2->3 q3->2 q4->1 q6->0 (r bits 4..0)

__device__ __forceinline__ float shx(float v, int m) { return __shfl_xor_sync(FULL, v, m); }

// ---- fused conv pair, both qubits reg bits (PA first, PB second) ----
template<int PA, int PB>
__device__ __forceinline__ void conv_rr(float (&st)[32], const float4* __restrict__ U4) {
    const float4 a0 = U4[0], a1 = U4[1], a2 = U4[2], a3 = U4[3];
    constexpr int ma = 1 << PA, mb = 1 << PB;
    #pragma unroll
    for (int r0 = 0; r0 < 32; ++r0) if (!(r0 & (ma | mb))) {
        const int i1 = r0 | mb, i2 = r0 | ma, i3 = r0 | ma | mb;
        float v0 = st[r0], v1 = st[i1], v2 = st[i2], v3 = st[i3];
        st[r0] = fmaf(a0.x, v0, fmaf(a0.y, v1, fmaf(a0.z, v2, a0.w * v3)));
        st[i1] = fmaf(a1.x, v0, fmaf(a1.y, v1, fmaf(a1.z, v2, a1.w * v3)));
        st[i2] = fmaf(a2.x, v0, fmaf(a2.y, v1, fmaf(a2.z, v2, a2.w * v3)));
        st[i3] = fmaf(a3.x, v0, fmaf(a3.y, v1, fmaf(a3.z, v2, a3.w * v3)));
    }
}

// ---- fused conv pair, one qubit on lane bit LBIT, one on reg bit PB.
// Coefficients pre-arranged in shared: T2[2a] = {u00,u01,u02,u03}, T2[2a+1] = {u10..u13}.
template<int LBIT, int PB>
__device__ __forceinline__ void conv_mx(float (&st)[32], const float4* __restrict__ T2, int lane) {
    constexpr int Lm = 1 << LBIT, mb = 1 << PB;
    const int a = (lane >> LBIT) & 1;
    const float4 ua = T2[2 * a];
    const float4 ub = T2[2 * a + 1];
    #pragma unroll
    for (int r0 = 0; r0 < 32; ++r0) if (!(r0 & mb)) {
        const int r1 = r0 | mb;
        float p0 = shx(st[r0], Lm), p1 = shx(st[r1], Lm);
        float o0 = st[r0], o1 = st[r1];
        st[r0] = fmaf(ua.x, o0, fmaf(ua.y, o1, fmaf(ua.z, p0, ua.w * p1)));
        st[r1] = fmaf(ub.x, o0, fmaf(ub.y, o1, fmaf(ub.z, p0, ub.w * p1)));
    }
}

__global__ __launch_bounds__(256, 3)
void qcnn_kernel(const float* __restrict__ x, const float* __restrict__ adj,
                 const float* __restrict__ w_proj, const float* __restrict__ b_proj,
                 const float* __restrict__ qp,
                 const float* __restrict__ w1, const float* __restrict__ b1,
                 const float* __restrict__ w2, const float* __restrict__ b2,
                 const float* __restrict__ w3, const float* __restrict__ b3,
                 float* __restrict__ out) {
    __shared__ alignas(16) float UUs[14][16];      // full fused conv matrices (rr gates)
    __shared__ alignas(16) float UMX[8][2][8];     // mx gates: [gate][laneBit a][8 coefs]
    __shared__ float poolc[4], pools[4];           // FULL-angle cos/sin of pool RYs
    __shared__ alignas(16) float w1s[512];         // w1 natural [64][8]
    __shared__ float4 w2p4[32 * 17];               // w2 rows padded to 68 floats
    __shared__ float4 h1buf4[CPB * 17];
    __shared__ float b1s[64], b2s[32], w3s[32];
    __shared__ float b3s;

    const int tid = threadIdx.x;

    // ---- build fused conv matrices U = C2 * G2 * C1 * G1 ----
    if (tid < 14) {
        const int layer = tid / 7, pi = tid - 7 * layer;
        const int base = layer * 28 + pi * 4;
        float c0, s0, c1, s1, c2, s2, c3, s3;
        sincosf(0.5f * qp[base + 0], &s0, &c0);
        sincosf(0.5f * qp[base + 1], &s1, &c1);
        sincosf(0.5f * qp[base + 2], &s2, &c2);
        sincosf(0.5f * qp[base + 3], &s3, &c3);
        float R0[2][2] = {{c0, -s0}, {s0, c0}};
        float R1[2][2] = {{c1, -s1}, {s1, c1}};
        float R2m[2][2] = {{c2, -s2}, {s2, c2}};
        float R3[2][2] = {{c3, -s3}, {s3, c3}};
        float A[4][4], G2m[4][4], Bm[4][4], Cm[4][4];
        #pragma unroll
        for (int ap = 0; ap < 2; ++ap)
        #pragma unroll
        for (int bp = 0; bp < 2; ++bp)
        #pragma unroll
        for (int aq = 0; aq < 2; ++aq)
        #pragma unroll
        for (int bq = 0; bq < 2; ++bq) {
            A[2 * ap + bp][2 * aq + bq]   = R0[ap][aq] * R1[bp][bq];
            G2m[2 * ap + bp][2 * aq + bq] = R2m[ap][aq] * R3[bp][bq];
        }
        const int sig1[4] = {0, 1, 3, 2};
        const int sig2[4] = {0, 3, 2, 1};
        #pragma unroll
        for (int xr = 0; xr < 4; ++xr)
            #pragma unroll
            for (int m = 0; m < 4; ++m) Bm[xr][m] = A[sig1[xr]][m];
        #pragma unroll
        for (int xr = 0; xr < 4; ++xr)
            #pragma unroll
            for (int m = 0; m < 4; ++m) {
                float acc = 0.f;
                #pragma unroll
                for (int y = 0; y < 4; ++y) acc = fmaf(G2m[xr][y], Bm[y][m], acc);
                Cm[xr][m] = acc;
            }
        float Uf[16];
        #pragma unroll
        for (int xr = 0; xr < 4; ++xr)
            #pragma unroll
            for (int m = 0; m < 4; ++m) {
                Uf[xr * 4 + m] = Cm[sig2[xr]][m];
                UUs[tid][xr * 4 + m] = Cm[sig2[xr]][m];
            }
        // mx-gate coefficient tables. gates-in-layer 0,2,3,6 are mixed;
        // LQ1 (lane qubit first in the pair) for 0 and 6.
        int mxslot = -1; bool lq1 = false;
        if (pi == 0) { mxslot = 0; lq1 = true; }
        else if (pi == 2) { mxslot = 1; lq1 = false; }
        else if (pi == 3) { mxslot = 2; lq1 = false; }
        else if (pi == 6) { mxslot = 3; lq1 = true; }
        if (mxslot >= 0) {
            #pragma unroll
            for (int a = 0; a < 2; ++a) {
                int r0, r1, d0, d1;
                if (lq1) { r0 = 2 * a; r1 = 2 * a + 1; d0 = 2 * (a ^ 1); d1 = d0 + 1; }
                else     { r0 = a;     r1 = 2 + a;     d0 = a ^ 1;       d1 = 2 + (a ^ 1); }
                float* dst = &UMX[layer * 4 + mxslot][a][0];
                dst[0] = Uf[r0 * 4 + r0]; dst[1] = Uf[r0 * 4 + r1];
                dst[2] = Uf[r0 * 4 + d0]; dst[3] = Uf[r0 * 4 + d1];
                dst[4] = Uf[r1 * 4 + r0]; dst[5] = Uf[r1 * 4 + r1];
                dst[6] = Uf[r1 * 4 + d0]; dst[7] = Uf[r1 * 4 + d1];
            }
        }
    }
    if (tid >= 16 && tid < 20) {
        float s, c;
        sincosf(qp[56 + 2 * (tid - 16)], &s, &c);   // FULL angle (fused pooling)
        poolc[tid - 16] = c; pools[tid - 16] = s;
    }
    for (int i = tid; i < 512; i += 256) w1s[i] = w1[i];
    for (int i = tid; i < 2048; i += 256) {
        int row = i >> 6, j = i & 63;
        ((float*)w2p4)[row * 68 + j] = w2[i];
    }
    if (tid < 64) b1s[tid] = b1[tid];
    if (tid >= 64 && tid < 96) b2s[tid - 64] = b2[tid - 64];
    if (tid >= 96 && tid < 128) w3s[tid - 96] = w3[tid - 96];
    if (tid == 20) b3s = b3[0];
    __syncthreads();

    const int wid = tid >> 5;
    const int lane = tid & 31;
    const int comp = (lane >> 3) & 1;         // 0 = re half, 1 = im half
    const int ci = lane >> 4;                 // circuit-in-warp (0/1)
    const int g = lane & 7;
    const int cb = wid * 2 + ci;              // circuit-in-block 0..15
    const int cir = blockIdx.x * CPB + cb;
    const int b = cir / N_;
    const int n = cir - b * N_;

    // ---- angle projection: lane computes angle q = g of its circuit ----
    float av;
    {
        av = b_proj[g];
        const float* wrow = w_proj + g * (S_ * F_);
        const float* xb = x + (size_t)b * (S_ * N_ * F_) + n * F_;
        #pragma unroll
        for (int s = 0; s < S_; ++s) {
            float2 xv = *(const float2*)(xb + s * (N_ * F_));
            av = fmaf(wrow[2 * s], xv.x, av);
            av = fmaf(wrow[2 * s + 1], xv.y, av);
        }
        av = fminf(fmaxf(av, -PI_F), PI_F);
    }
    float sv, cv;
    __sincosf(0.5f * av, &sv, &cv);
    float ch[8], sh[8];
    #pragma unroll
    for (int q = 0; q < 8; ++q) {
        ch[q] = __shfl_sync(FULL, cv, (lane & 24) | q);
        sh[q] = __shfl_sync(FULL, sv, (lane & 24) | q);
    }

    // ---- graph CNOT mask ----
    const int c = n & 7;
    const int pcq = (0x50612347u >> (4 * c)) & 0xF;    // posOf[c]
    int cond = (adj[c * N_ + g] > 0.f) && (g != c);
    const unsigned bal = __ballot_sync(FULL, cond);
    const unsigned mask8 = (bal >> (lane & 24)) & 0xFFu;
    constexpr int posOf[8] = {7, 4, 3, 2, 1, 6, 0, 5};
    int M = 0;
    #pragma unroll
    for (int t = 0; t < 8; ++t) M |= (int)((mask8 >> t) & 1u) << posOf[t];
    const int glm = (M >> 5) & 7;
    const int MR = M & 31;
    unsigned bcmask = (pcq == 0) ? 0xAAAAAAAAu : (pcq == 1) ? 0xCCCCCCCCu :
                      (pcq == 2) ? 0xF0F0F0F0u : (pcq == 3) ? 0xFF00FF00u : 0xFFFF0000u;
    if (pcq >= 5) bcmask = ((g >> (pcq - 5)) & 1) ? 0xFFFFFFFFu : 0u;

    // ---- build product state DIRECTLY PERMUTED by the graph CNOTs ----
    const int bq0 = (g >> 2) & 1, bq5 = (g >> 1) & 1, bq7 = g & 1;
    const int gp = g ^ glm;
    const int pp0 = (gp >> 2) & 1, pp5 = (gp >> 1) & 1, pp7 = gp & 1;

    const float magL0 = (bq0 ? sh[0] : ch[0]) * (bq5 ? sh[5] : ch[5]) * (bq7 ? sh[7] : ch[7]);
    const float magL1 = (pp0 ? sh[0] : ch[0]) * (pp5 ? sh[5] : ch[5]) * (pp7 ? sh[7] : ch[7]);
    const float ssA = bq0 ? sh[4] : -sh[4];
    const float ssB = pp0 ? sh[4] : -sh[4];
    const float ssx0 = comp ? ssA : -ssA;
    const float ssx1 = comp ? ssB : -ssB;

    float u23r[4], u23i[4];
    #pragma unroll
    for (int k = 0; k < 4; ++k) {
        const float s6 = (k & 2) ? sh[6] : -sh[6];
        const float s7 = (k & 1) ? sh[7] : -sh[7];
        u23r[k] = fmaf(ch[6], ch[7], -s6 * s7);
        u23i[k] = fmaf(ch[6], s7, s6 * ch[7]);
    }
    float B0[8], B1[8];
    #pragma unroll
    for (int t = 0; t < 8; ++t) {
        const float s5 = (t & 4) ? sh[5] : -sh[5];
        const float ur = fmaf(ch[5], u23r[t & 3], -s5 * u23i[t & 3]);
        const float ui = fmaf(ch[5], u23i[t & 3], s5 * u23r[t & 3]);
        const float P = comp ? ui : ur;
        const float Q = comp ? ur : ui;
        const float mg = ((t & 4) ? sh[1] : ch[1]) * ((t & 2) ? sh[2] : ch[2])
                       * ((t & 1) ? sh[3] : ch[3]);
        B0[t] = magL0 * mg * fmaf(ch[4], P, ssx0 * Q);
        B1[t] = magL1 * mg * fmaf(ch[4], P, ssx1 * Q);
    }
    const int Mt = (MR >> 2) & 7, Mlr = MR & 3;
    float Bp[8];
    {
        float ta[8], tb[8];
        #pragma unroll
        for (int t = 0; t < 8; ++t) ta[t] = (Mt & 1) ? B1[t ^ 1] : B1[t];
        #pragma unroll
        for (int t = 0; t < 8; ++t) tb[t] = (Mt & 2) ? ta[t ^ 2] : ta[t];
        #pragma unroll
        for (int t = 0; t < 8; ++t) Bp[t] = (Mt & 4) ? tb[t ^ 4] : tb[t];
    }
    float mA[4], mp[4];
    mA[0] = ch[4] * ch[6]; mA[1] = ch[4] * sh[6];
    mA[2] = sh[4] * ch[6]; mA[3] = sh[4] * sh[6];
    {
        float tm[4];
        #pragma unroll
        for (int l = 0; l < 4; ++l) tm[l] = (Mlr & 1) ? mA[l ^ 1] : mA[l];
        #pragma unroll
        for (int l = 0; l < 4; ++l) mp[l] = (Mlr & 2) ? tm[l ^ 2] : tm[l];
    }
    float st[32];
    #pragma unroll
    for (int t = 0; t < 8; ++t)
        #pragma unroll
        for (int l = 0; l < 4; ++l) {
            const int r = 4 * t + l;
            const bool bc = (bcmask >> r) & 1u;
            st[r] = (bc ? Bp[t] : B0[t]) * (bc ? mp[l] : mA[l]);
        }

    // ---- 2 conv layers ----
    #pragma unroll
    for (int l = 0; l < 2; ++l) {
        const float4* Ub = (const float4*)UUs[l * 7];
        conv_mx<2, 4>(st, (const float4*)UMX[l * 4 + 0], lane);   // (q0,q1)
        conv_rr<3, 2>(st, Ub + 1 * 4);                            // (q2,q3)
        conv_mx<1, 1>(st, (const float4*)UMX[l * 4 + 1], lane);   // (q4,q5)
        conv_mx<0, 0>(st, (const float4*)UMX[l * 4 + 2], lane);   // (q6,q7)
        conv_rr<4, 3>(st, Ub + 4 * 4);                            // (q1,q2)
        conv_rr<2, 1>(st, Ub + 5 * 4);                            // (q3,q4)
        conv_mx<1, 0>(st, (const float4*)UMX[l * 4 + 3], lane);   // (q5,q6)
    }

    // ---- measurement with POOLING FUSED IN ----
    float x2 = 0.f, x4 = 0.f, x6 = 0.f, c0x = 0.f;
    #pragma unroll
    for (int r = 0; r < 32; ++r) {
        if (!(r & 8)) x2 = fmaf(st[r], st[r | 8], x2);   // q2 pairs
        if (!(r & 2)) x4 = fmaf(st[r], st[r | 2], x4);   // q4 pairs
        if (!(r & 1)) x6 = fmaf(st[r], st[r | 1], x6);   // q6 pairs
        c0x = fmaf(st[r], shx(st[r], 4), c0x);           // q0 cross (lane bit 2)
    }
    // Walsh tree for tot, z1..z4, z6 (r bits: 4=q1, 3=q2, 2=q3, 1=q4, 0=q6)
    float s0[16], e6 = 0.f;
    #pragma unroll
    for (int k = 0; k < 16; ++k) {
        float pe = st[2 * k] * st[2 * k];
        float po = st[2 * k + 1] * st[2 * k + 1];
        s0[k] = pe + po;
        e6 += pe;
    }
    float s1[8], e4 = 0.f;
    #pragma unroll
    for (int m = 0; m < 8; ++m) { s1[m] = s0[2 * m] + s0[2 * m + 1]; e4 += s0[2 * m]; }
    float s2[4], e3 = 0.f;
    #pragma unroll
    for (int n2 = 0; n2 < 4; ++n2) { s2[n2] = s1[2 * n2] + s1[2 * n2 + 1]; e3 += s1[2 * n2]; }
    const float e2 = s2[0] + s2[2];
    const float s3a = s2[0] + s2[1], s3b = s2[2] + s2[3];
    const float tot = s3a + s3b;
    const float z1 = s3a - s3b;
    const float z2r = fmaf(2.f, e2, -tot);
    const float z3r = fmaf(2.f, e3, -tot);
    const float z4r = fmaf(2.f, e4, -tot);
    const float z6r = fmaf(2.f, e6, -tot);

    float z[8];
    z[0] = fmaf(poolc[0], (bq0 ? -tot : tot), -pools[0] * c0x);
    z[2] = fmaf(poolc[1], z2r, -2.f * pools[1] * x2);
    z[4] = fmaf(poolc[2], z4r, -2.f * pools[2] * x4);
    z[6] = fmaf(poolc[3], z6r, -2.f * pools[3] * x6);
    z[1] = z1; z[3] = z3r;
    z[5] = bq5 ? -tot : tot;
    z[7] = bq7 ? -tot : tot;

    // ---- reduce-scatter over the 8-lane group: lane g ends with Z_comp[g] ----
    float zg;
    {
        const int b2l = bq0, b1l = bq5, b0l = bq7;   // lane bits 2,1,0
        float v[4];
        #pragma unroll
        for (int j = 0; j < 4; ++j) {
            float keep = b2l ? z[j + 4] : z[j];
            float send = b2l ? z[j] : z[j + 4];
            v[j] = keep + shx(send, 4);
        }
        float u0 = (b1l ? v[2] : v[0]) + shx(b1l ? v[0] : v[2], 2);
        float u1 = (b1l ? v[3] : v[1]) + shx(b1l ? v[1] : v[3], 2);
        zg = (b0l ? u1 : u0) + shx(b0l ? u0 : u1, 1);
    }
    // combine re + im halves of this circuit: one intra-warp butterfly
    zg += shx(zg, 8);

    // ---- MLP head: 8 -> 64 -> 32 -> 1, ALL 16 lanes of the circuit work ----
    const int hl = lane & 15;                  // 0..15 within circuit
    float z8[8];
    #pragma unroll
    for (int w = 0; w < 8; ++w)
        z8[w] = __shfl_sync(FULL, zg, (lane & 16) | w);

    // h1: this lane computes rows 4*hl .. 4*hl+3
    float h1v[4];
    #pragma unroll
    for (int i = 0; i < 4; ++i) {
        const int row = 4 * hl + i;
        float4 wa = *(const float4*)(w1s + row * 8);
        float4 wb = *(const float4*)(w1s + row * 8 + 4);
        float acc = b1s[row];
        acc = fmaf(wa.x, z8[0], acc); acc = fmaf(wa.y, z8[1], acc);
        acc = fmaf(wa.z, z8[2], acc); acc = fmaf(wa.w, z8[3], acc);
        acc = fmaf(wb.x, z8[4], acc); acc = fmaf(wb.y, z8[5], acc);
        acc = fmaf(wb.z, z8[6], acc); acc = fmaf(wb.w, z8[7], acc);
        h1v[i] = fmaxf(acc, 0.f);
    }
    *(float4*)((float*)h1buf4 + cb * 68 + 4 * hl) =
        make_float4(h1v[0], h1v[1], h1v[2], h1v[3]);
    __syncwarp();

    // h2: this lane computes rows hl and hl+16
    float acc2a = b2s[hl], acc2b = b2s[hl + 16];
    const float4* h1p = h1buf4 + cb * 17;
    #pragma unroll
    for (int j4 = 0; j4 < 16; ++j4) {
        float4 h = h1p[j4];
        float4 wa = w2p4[hl * 17 + j4];
        float4 wb = w2p4[(hl + 16) * 17 + j4];
        acc2a = fmaf(wa.x, h.x, fmaf(wa.y, h.y, fmaf(wa.z, h.z, fmaf(wa.w, h.w, acc2a))));
        acc2b = fmaf(wb.x, h.x, fmaf(wb.y, h.y, fmaf(wb.z, h.z, fmaf(wb.w, h.w, acc2b))));
    }
    float o = fmaf(w3s[hl], fmaxf(acc2a, 0.f), w3s[hl + 16] * fmaxf(acc2b, 0.f));
    o += shx(o, 1); o += shx(o, 2); o += shx(o, 4); o += shx(o, 8);
    if (hl == 0) out[cir] = o + b3s;
}

extern "C" void kernel_launch(void* const* d_in, const int* in_sizes, int n_in,
                              void* d_out, int out_size) {
    const float* x      = (const float*)d_in[0];
    const float* adj    = (const float*)d_in[1];
    const float* w_proj = (const float*)d_in[2];
    const float* b_proj = (const float*)d_in[3];
    const float* qp     = (const float*)d_in[4];
    const float* w1     = (const float*)d_in[5];
    const float* b1     = (const float*)d_in[6];
    const float* w2     = (const float*)d_in[7];
    const float* b2     = (const float*)d_in[8];
    const float* w3     = (const float*)d_in[9];
    const float* b3     = (const float*)d_in[10];
    float* out = (float*)d_out;

    const int blocks = NCIRC / CPB;   // 828
    qcnn_kernel<<<blocks, 256>>>(x, adj, w_proj, b_proj, qp,
                                 w1, b1, w2, b2, w3, b3, out);
}